// round 7
// baseline (speedup 1.0000x reference)
#include <cuda_runtime.h>
#include <cstdint>

// out[n, d, b] = unique_weights[indices[n], d] * input_values[n, d, b]
// N=16384, U=1024, D=128, B=16, fp32.  256 MiB compulsory HBM traffic.
//
// Structural change vs R2 plateau (44.3us, DRAM 61%): input is staged through
// SMEM with cp.async.bulk (TMA bulk path) in 16 KiB bursts, depth-2 mbarrier
// ring per CTA. Goal: large sequential DRAM read bursts + deep TMA queues
// instead of fine-grained per-warp LDG. Stores remain coalesced STG.

#define N_POS 16384
#define U_DIM 1024
#define D_DIM 128
#define B_DIM 16

#define TILE_BYTES  16384                 // 16 KiB per bulk copy
#define TILE_F4     (TILE_BYTES / 16)     // 1024 float4 per tile
#define THREADS     256                   // 4 float4 per thread per tile
#define N_TILES     (N_POS * D_DIM * B_DIM * 4 / TILE_BYTES)  // 8192

__device__ __forceinline__ uint32_t smem_u32(const void* p) {
    uint32_t a;
    asm("{ .reg .u64 t; cvta.to.shared.u64 t, %1; cvt.u32.u64 %0, t; }"
        : "=r"(a) : "l"(p));
    return a;
}

__device__ __forceinline__ void mbar_init(uint32_t mbar, uint32_t count) {
    asm volatile("mbarrier.init.shared.b64 [%0], %1;" :: "r"(mbar), "r"(count) : "memory");
}

__device__ __forceinline__ void mbar_expect_tx(uint32_t mbar, uint32_t bytes) {
    asm volatile("mbarrier.arrive.expect_tx.shared.b64 _, [%0], %1;"
                 :: "r"(mbar), "r"(bytes) : "memory");
}

__device__ __forceinline__ void bulk_g2s(uint32_t dst_smem, const void* src_gmem,
                                         uint32_t bytes, uint32_t mbar) {
    asm volatile("cp.async.bulk.shared::cluster.global.mbarrier::complete_tx::bytes "
                 "[%0], [%1], %2, [%3];"
                 :: "r"(dst_smem), "l"(src_gmem), "r"(bytes), "r"(mbar) : "memory");
}

__device__ __forceinline__ void mbar_wait(uint32_t mbar, uint32_t parity) {
    asm volatile(
        "{\n\t"
        ".reg .pred P;\n\t"
        "WAIT_%=:\n\t"
        "mbarrier.try_wait.parity.acquire.cta.shared::cta.b64 P, [%0], %1, 0x989680;\n\t"
        "@P bra.uni DONE_%=;\n\t"
        "bra.uni WAIT_%=;\n\t"
        "DONE_%=:\n\t"
        "}"
        :: "r"(mbar), "r"(parity) : "memory");
}

__global__ void __launch_bounds__(THREADS) diag_scale_tma_kernel(
    const float* __restrict__ x,          // [N, D, B]
    const float* __restrict__ w,          // [U, D]
    const int* __restrict__ idx,          // [N] (int32)
    float* __restrict__ out)              // [N, D, B]
{
    __shared__ alignas(128) float4 buf[2][TILE_F4];   // 2 x 16 KiB
    __shared__ alignas(8) unsigned long long mbar_s[2];

    const int tid = threadIdx.x;
    const uint32_t mb0 = smem_u32(&mbar_s[0]);
    const uint32_t mb1 = smem_u32(&mbar_s[1]);
    const uint32_t bufa0 = smem_u32(&buf[0][0]);
    const uint32_t bufa1 = smem_u32(&buf[1][0]);

    if (tid == 0) {
        mbar_init(mb0, 1);
        mbar_init(mb1, 1);
    }
    __syncthreads();

    const int G = gridDim.x;
    const int t0 = blockIdx.x;

    // Prologue: prefetch first two tiles.
    if (tid == 0) {
        if (t0 < N_TILES) {
            mbar_expect_tx(mb0, TILE_BYTES);
            bulk_g2s(bufa0, (const char*)x + (size_t)t0 * TILE_BYTES, TILE_BYTES, mb0);
        }
        if (t0 + G < N_TILES) {
            mbar_expect_tx(mb1, TILE_BYTES);
            bulk_g2s(bufa1, (const char*)x + (size_t)(t0 + G) * TILE_BYTES, TILE_BYTES, mb1);
        }
    }

    int ph0 = 0, ph1 = 0;
    int k = 0;
    for (int t = t0; t < N_TILES; t += G, k++) {
        const int s = k & 1;
        const uint32_t mb = s ? mb1 : mb0;

        // Wait for this tile's data.
        if (s) { mbar_wait(mb, ph1); ph1 ^= 1; }
        else   { mbar_wait(mb, ph0); ph0 ^= 1; }

        const float4* __restrict__ bp = buf[s];
        float4* __restrict__ op = reinterpret_cast<float4*>(out) + (size_t)t * TILE_F4;
        const unsigned int gbase = (unsigned int)t * TILE_F4;

        // 4 float4 per thread, consecutive lanes -> consecutive 16B (conflict-free
        // LDS.128, fully coalesced STG.128).
        float4 v[4];
        float  wv[4];
        #pragma unroll
        for (int j = 0; j < 4; j++) {
            const int f4i = tid + j * THREADS;
            v[j] = bp[f4i];
            const unsigned int row = (gbase + (unsigned int)f4i) >> 2;  // 4 f4 per row
            const unsigned int n = row >> 7;
            const unsigned int d = row & 127;
            const unsigned int u = (unsigned int)__ldg(&idx[n]) & (U_DIM - 1);
            wv[j] = __ldg(&w[(size_t)u * D_DIM + d]);
        }
        #pragma unroll
        for (int j = 0; j < 4; j++) {
            const int f4i = tid + j * THREADS;
            float4 r = v[j];
            r.x *= wv[j]; r.y *= wv[j]; r.z *= wv[j]; r.w *= wv[j];
            op[f4i] = r;
        }

        __syncthreads();   // everyone done reading buf[s]; safe to refill

        const int tn = t + 2 * G;
        if (tn < N_TILES && tid == 0) {
            mbar_expect_tx(mb, TILE_BYTES);
            bulk_g2s(s ? bufa1 : bufa0,
                     (const char*)x + (size_t)tn * TILE_BYTES, TILE_BYTES, mb);
        }
    }
}

extern "C" void kernel_launch(void* const* d_in, const int* in_sizes, int n_in,
                              void* d_out, int out_size)
{
    // Bind by element count — robust to metadata ordering.
    const float* x = nullptr;    // N*D*B = 33,554,432
    const float* w = nullptr;    // U*D   = 131,072
    const int* idx = nullptr;    // N     = 16,384
    for (int i = 0; i < n_in; i++) {
        if (in_sizes[i] == N_POS * D_DIM * B_DIM)   x   = (const float*)d_in[i];
        else if (in_sizes[i] == U_DIM * D_DIM)      w   = (const float*)d_in[i];
        else if (in_sizes[i] == N_POS)              idx = (const int*)d_in[i];
    }
    float* out = (float*)d_out;

    // ~7 CTAs/SM (32KB smem each) x 148 SMs; grid-stride over 8192 tiles.
    const int blocks = 1036;
    diag_scale_tma_kernel<<<blocks, THREADS>>>(x, w, idx, out);
}